// round 2
// baseline (speedup 1.0000x reference)
#include <cuda_runtime.h>

// Problem constants
#define BB 2
#define SS 2048
#define DD 1024
#define HH 16
#define HD 64
#define N3 (3 * DD)     // 3072
#define MROWS (BB * SS) // 4096

// d_out layout (concatenated flattened outputs, in reference return order)
#define A_SZ   ((long long)BB * SS * DD)           // 4,194,304
#define P_HALF ((long long)BB * HH * SS * HD)      // 4,194,304
#define P_OFF  (A_SZ)
#define ATTN_OFF (A_SZ + 2 * P_HALF)               // 12,582,912

// Scratch (device globals — no allocations allowed)
__device__ float g_q[BB * HH * SS * HD];   // q in [B,H,S,hd]
__device__ float g_ah[MROWS * DD];         // merged-head attention output [B*S, D]

// ---------------------------------------------------------------------------
// Kernel 1: QKV projection. x[4096,1024] @ w_attn[1024,3072] + b_attn.
// 128x64 tile per block, 256 threads, 8x4 per thread, K-tile 16.
// Epilogue scatters q -> g_q, k/v -> present region of d_out ([B,H,S,hd]).
// ---------------------------------------------------------------------------
__global__ __launch_bounds__(256) void qkv_gemm(const float* __restrict__ x,
                                                const float* __restrict__ w,
                                                const float* __restrict__ bias,
                                                float* __restrict__ out) {
    __shared__ float As[128][17];
    __shared__ float Bs[16][68];
    const int tid = threadIdx.x;
    const int tx = tid & 15, ty = tid >> 4;
    const int rbase = blockIdx.y * 128;
    const int nbase = blockIdx.x * 64;

    float acc[8][4];
#pragma unroll
    for (int i = 0; i < 8; i++)
#pragma unroll
        for (int j = 0; j < 4; j++) acc[i][j] = 0.f;

    for (int kb = 0; kb < DD; kb += 16) {
        // load A tile: 128x16
#pragma unroll
        for (int i = tid; i < 512; i += 256) {
            int r = i >> 2, c = (i & 3) << 2;
            float4 v = *(const float4*)&x[(long long)(rbase + r) * DD + kb + c];
            As[r][c + 0] = v.x; As[r][c + 1] = v.y;
            As[r][c + 2] = v.z; As[r][c + 3] = v.w;
        }
        // load B tile: 16x64
        {
            int k = tid >> 4, c = (tid & 15) << 2;
            *(float4*)&Bs[k][c] = *(const float4*)&w[(long long)(kb + k) * N3 + nbase + c];
        }
        __syncthreads();
#pragma unroll
        for (int k = 0; k < 16; k++) {
            float a[8];
#pragma unroll
            for (int i = 0; i < 8; i++) a[i] = As[ty * 8 + i][k];
            float4 bv = *(float4*)&Bs[k][tx * 4];
#pragma unroll
            for (int i = 0; i < 8; i++) {
                acc[i][0] += a[i] * bv.x;
                acc[i][1] += a[i] * bv.y;
                acc[i][2] += a[i] * bv.z;
                acc[i][3] += a[i] * bv.w;
            }
        }
        __syncthreads();
    }

    // epilogue: bias + scatter
    float bj[4];
#pragma unroll
    for (int j = 0; j < 4; j++) bj[j] = bias[nbase + tx * 4 + j];

#pragma unroll
    for (int i = 0; i < 8; i++) {
        int row = rbase + ty * 8 + i;
        int b = row >> 11, s = row & 2047;
#pragma unroll
        for (int j = 0; j < 4; j++) {
            int col = nbase + tx * 4 + j;
            float v = acc[i][j] + bj[j];
            int which = col >> 10;
            int d = col & 1023;
            int h = d >> 6, e = d & 63;
            long long idx = (((long long)(b * HH + h)) * SS + s) * HD + e;
            if (which == 0)      g_q[idx] = v;
            else if (which == 1) out[P_OFF + idx] = v;            // present[0] = k
            else                 out[P_OFF + P_HALF + idx] = v;   // present[1] = v
        }
    }
}

// ---------------------------------------------------------------------------
// Kernel 2: causal attention for one (b, h, 64-query-row tile).
// Phase A: denominators (no max-shift needed: scores are O(1)).
// Phase B: recompute scores, write normalized attn, accumulate attn@V.
// ---------------------------------------------------------------------------
#define SMP 68
#define ATTN_SMEM (4 * 64 * SMP * 4 + 64 * 4)

__global__ __launch_bounds__(256) void attn_kernel(float* __restrict__ out) {
    extern __shared__ float sm[];
    float* sQ = sm;
    float* sK = sm + 64 * SMP;
    float* sV = sm + 2 * 64 * SMP;
    float* sS = sm + 3 * 64 * SMP;
    float* rs = sm + 4 * 64 * SMP;

    const int tid = threadIdx.x;
    const int tx = tid & 15, ty = tid >> 4;
    const int qt = blockIdx.x, h = blockIdx.y, b = blockIdx.z;
    const int qbase = qt * 64;
    const long long headoff = ((long long)(b * HH + h)) * SS * HD;

    const float* qptr = g_q + headoff + (long long)qbase * HD;
    const float* kptr = out + P_OFF + headoff;
    const float* vptr = out + P_OFF + P_HALF + headoff;
    float* attn_out = out + ATTN_OFF + ((long long)(b * HH + h)) * SS * SS;

    // load Q tile (64x64)
#pragma unroll
    for (int i = tid; i < 1024; i += 256) {
        int r = i >> 4, c = (i & 15) << 2;
        *(float4*)&sQ[r * SMP + c] = *(const float4*)&qptr[r * HD + c];
    }

    const int r0 = ty * 4;
    const int c0 = tx * 4;

    // ---------------- Phase A: row denominators ----------------
    float rpart[4] = {0.f, 0.f, 0.f, 0.f};
    for (int kt = 0; kt <= qt; kt++) {
        __syncthreads();
#pragma unroll
        for (int i = tid; i < 1024; i += 256) {
            int r = i >> 4, c = (i & 15) << 2;
            *(float4*)&sK[r * SMP + c] = *(const float4*)&kptr[(kt * 64 + r) * HD + c];
        }
        __syncthreads();

        float acc[4][4];
#pragma unroll
        for (int i = 0; i < 4; i++)
#pragma unroll
            for (int j = 0; j < 4; j++) acc[i][j] = 0.f;

#pragma unroll 4
        for (int d = 0; d < 64; d++) {
            float qf[4], kf[4];
#pragma unroll
            for (int i = 0; i < 4; i++) qf[i] = sQ[(r0 + i) * SMP + d];
#pragma unroll
            for (int j = 0; j < 4; j++) kf[j] = sK[(c0 + j) * SMP + d];
#pragma unroll
            for (int i = 0; i < 4; i++)
#pragma unroll
                for (int j = 0; j < 4; j++) acc[i][j] += qf[i] * kf[j];
        }
        const bool diag = (kt == qt);
#pragma unroll
        for (int i = 0; i < 4; i++)
#pragma unroll
            for (int j = 0; j < 4; j++) {
                float e = (diag && (c0 + j > r0 + i)) ? 0.f
                                                      : __expf(acc[i][j] * 0.125f);
                rpart[i] += e;
            }
    }
    // reduce across the 16 tx lanes (same ty stays within half-warp)
#pragma unroll
    for (int i = 0; i < 4; i++) {
        rpart[i] += __shfl_xor_sync(0xFFFFFFFFu, rpart[i], 1);
        rpart[i] += __shfl_xor_sync(0xFFFFFFFFu, rpart[i], 2);
        rpart[i] += __shfl_xor_sync(0xFFFFFFFFu, rpart[i], 4);
        rpart[i] += __shfl_xor_sync(0xFFFFFFFFu, rpart[i], 8);
    }
    if (tx == 0) {
#pragma unroll
        for (int i = 0; i < 4; i++) rs[r0 + i] = rpart[i];
    }
    __syncthreads();
    float rinv[4];
#pragma unroll
    for (int i = 0; i < 4; i++) rinv[i] = 1.0f / rs[r0 + i];

    // ---------------- Phase B: write attn + attn@V ----------------
    float ao[4][4];
#pragma unroll
    for (int i = 0; i < 4; i++)
#pragma unroll
        for (int j = 0; j < 4; j++) ao[i][j] = 0.f;

    for (int kt = 0; kt <= qt; kt++) {
        __syncthreads();
#pragma unroll
        for (int i = tid; i < 2048; i += 256) {
            int r = (i >> 4) & 63, c = (i & 15) << 2;
            if (i < 1024)
                *(float4*)&sK[r * SMP + c] = *(const float4*)&kptr[(kt * 64 + r) * HD + c];
            else
                *(float4*)&sV[r * SMP + c] = *(const float4*)&vptr[(kt * 64 + r) * HD + c];
        }
        __syncthreads();

        float acc[4][4];
#pragma unroll
        for (int i = 0; i < 4; i++)
#pragma unroll
            for (int j = 0; j < 4; j++) acc[i][j] = 0.f;

#pragma unroll 4
        for (int d = 0; d < 64; d++) {
            float qf[4], kf[4];
#pragma unroll
            for (int i = 0; i < 4; i++) qf[i] = sQ[(r0 + i) * SMP + d];
#pragma unroll
            for (int j = 0; j < 4; j++) kf[j] = sK[(c0 + j) * SMP + d];
#pragma unroll
            for (int i = 0; i < 4; i++)
#pragma unroll
                for (int j = 0; j < 4; j++) acc[i][j] += qf[i] * kf[j];
        }
        const bool diag = (kt == qt);
#pragma unroll
        for (int i = 0; i < 4; i++) {
#pragma unroll
            for (int j = 0; j < 4; j++) {
                float e = (diag && (c0 + j > r0 + i)) ? 0.f
                                                      : __expf(acc[i][j] * 0.125f);
                acc[i][j] = e * rinv[i];
            }
            float4 av = make_float4(acc[i][0], acc[i][1], acc[i][2], acc[i][3]);
            *(float4*)&sS[(r0 + i) * SMP + c0] = av;
            *(float4*)&attn_out[(long long)(qbase + r0 + i) * SS + kt * 64 + c0] = av;
        }
        __syncthreads();

        // AV: ao[r][e] += sS[r][j] * sV[j][e]
#pragma unroll 2
        for (int j = 0; j < 64; j++) {
            float sv[4];
#pragma unroll
            for (int i = 0; i < 4; i++) sv[i] = sS[(r0 + i) * SMP + j];
            float4 vv = *(float4*)&sV[j * SMP + c0];
#pragma unroll
            for (int i = 0; i < 4; i++) {
                ao[i][0] += sv[i] * vv.x;
                ao[i][1] += sv[i] * vv.y;
                ao[i][2] += sv[i] * vv.z;
                ao[i][3] += sv[i] * vv.w;
            }
        }
    }

    // zero-fill strictly-upper attn tiles
    float4 z = make_float4(0.f, 0.f, 0.f, 0.f);
    for (int col = (qt + 1) * 64 + c0; col < SS; col += 64) {
#pragma unroll
        for (int i = 0; i < 4; i++)
            *(float4*)&attn_out[(long long)(qbase + r0 + i) * SS + col] = z;
    }

    // write merged-head output to scratch
#pragma unroll
    for (int i = 0; i < 4; i++) {
        float4 av = make_float4(ao[i][0], ao[i][1], ao[i][2], ao[i][3]);
        *(float4*)&g_ah[((long long)(b * SS + qbase + r0 + i)) * DD + h * HD + c0] = av;
    }
}

// ---------------------------------------------------------------------------
// Kernel 3: output projection. g_ah[4096,1024] @ w_proj[1024,1024] + b_proj.
// ---------------------------------------------------------------------------
__global__ __launch_bounds__(256) void proj_gemm(const float* __restrict__ w,
                                                 const float* __restrict__ bias,
                                                 float* __restrict__ out) {
    __shared__ float As[128][17];
    __shared__ float Bs[16][68];
    const int tid = threadIdx.x;
    const int tx = tid & 15, ty = tid >> 4;
    const int rbase = blockIdx.y * 128;
    const int nbase = blockIdx.x * 64;

    float acc[8][4];
#pragma unroll
    for (int i = 0; i < 8; i++)
#pragma unroll
        for (int j = 0; j < 4; j++) acc[i][j] = 0.f;

    for (int kb = 0; kb < DD; kb += 16) {
#pragma unroll
        for (int i = tid; i < 512; i += 256) {
            int r = i >> 2, c = (i & 3) << 2;
            float4 v = *(const float4*)&g_ah[(long long)(rbase + r) * DD + kb + c];
            As[r][c + 0] = v.x; As[r][c + 1] = v.y;
            As[r][c + 2] = v.z; As[r][c + 3] = v.w;
        }
        {
            int k = tid >> 4, c = (tid & 15) << 2;
            *(float4*)&Bs[k][c] = *(const float4*)&w[(long long)(kb + k) * DD + nbase + c];
        }
        __syncthreads();
#pragma unroll
        for (int k = 0; k < 16; k++) {
            float a[8];
#pragma unroll
            for (int i = 0; i < 8; i++) a[i] = As[ty * 8 + i][k];
            float4 bv = *(float4*)&Bs[k][tx * 4];
#pragma unroll
            for (int i = 0; i < 8; i++) {
                acc[i][0] += a[i] * bv.x;
                acc[i][1] += a[i] * bv.y;
                acc[i][2] += a[i] * bv.z;
                acc[i][3] += a[i] * bv.w;
            }
        }
        __syncthreads();
    }

    float bj[4];
#pragma unroll
    for (int j = 0; j < 4; j++) bj[j] = bias[nbase + tx * 4 + j];
#pragma unroll
    for (int i = 0; i < 8; i++) {
        int row = rbase + ty * 8 + i;
        float4 v = make_float4(acc[i][0] + bj[0], acc[i][1] + bj[1],
                               acc[i][2] + bj[2], acc[i][3] + bj[3]);
        *(float4*)&out[(long long)row * DD + nbase + tx * 4] = v;
    }
}

// ---------------------------------------------------------------------------
extern "C" void kernel_launch(void* const* d_in, const int* in_sizes, int n_in,
                              void* d_out, int out_size) {
    const float* x      = (const float*)d_in[0];
    const float* w_attn = (const float*)d_in[1];
    const float* b_attn = (const float*)d_in[2];
    const float* w_proj = (const float*)d_in[3];
    const float* b_proj = (const float*)d_in[4];
    float* out = (float*)d_out;

    cudaFuncSetAttribute(attn_kernel, cudaFuncAttributeMaxDynamicSharedMemorySize,
                         ATTN_SMEM);

    // 1) QKV projection: writes g_q and present(k,v) in d_out
    qkv_gemm<<<dim3(N3 / 64, MROWS / 128), 256>>>(x, w_attn, b_attn, out);

    // 2) attention: writes attn region of d_out and g_ah
    attn_kernel<<<dim3(SS / 64, HH, BB), 256, ATTN_SMEM>>>(out);

    // 3) output projection: writes a region of d_out
    proj_gemm<<<dim3(DD / 64, MROWS / 128), 256>>>(w_proj, b_proj, out);
}

// round 3
// speedup vs baseline: 1.0620x; 1.0620x over previous
#include <cuda_runtime.h>

// Problem constants
#define BB 2
#define SS 2048
#define DD 1024
#define HH 16
#define HD 64
#define N3 (3 * DD)     // 3072
#define MROWS (BB * SS) // 4096

// d_out layout (concatenated flattened outputs, in reference return order)
#define A_SZ   ((long long)BB * SS * DD)           // 4,194,304
#define P_HALF ((long long)BB * HH * SS * HD)      // 4,194,304
#define P_OFF  (A_SZ)
#define ATTN_OFF (A_SZ + 2 * P_HALF)               // 12,582,912

// Scratch (device globals — no allocations allowed)
__device__ float g_q[BB * HH * SS * HD];   // q in [B,H,S,hd]
__device__ float g_ah[MROWS * DD];         // merged-head attention output [B*S, D]

// ---------------------------------------------------------------------------
// Kernel 1: QKV projection. x[4096,1024] @ w_attn[1024,3072] + b_attn.
// 128x64 tile per block, 256 threads, 8x4 per thread, K-tile 16.
// Epilogue scatters q -> g_q, k/v -> present region of d_out ([B,H,S,hd]).
// ---------------------------------------------------------------------------
__global__ __launch_bounds__(256) void qkv_gemm(const float* __restrict__ x,
                                                const float* __restrict__ w,
                                                const float* __restrict__ bias,
                                                float* __restrict__ out) {
    __shared__ float As[128][17];
    __shared__ float Bs[16][68];
    const int tid = threadIdx.x;
    const int tx = tid & 15, ty = tid >> 4;
    const int rbase = blockIdx.y * 128;
    const int nbase = blockIdx.x * 64;

    float acc[8][4];
#pragma unroll
    for (int i = 0; i < 8; i++)
#pragma unroll
        for (int j = 0; j < 4; j++) acc[i][j] = 0.f;

    for (int kb = 0; kb < DD; kb += 16) {
        // load A tile: 128x16
#pragma unroll
        for (int i = tid; i < 512; i += 256) {
            int r = i >> 2, c = (i & 3) << 2;
            float4 v = *(const float4*)&x[(long long)(rbase + r) * DD + kb + c];
            As[r][c + 0] = v.x; As[r][c + 1] = v.y;
            As[r][c + 2] = v.z; As[r][c + 3] = v.w;
        }
        // load B tile: 16x64
        {
            int k = tid >> 4, c = (tid & 15) << 2;
            *(float4*)&Bs[k][c] = *(const float4*)&w[(long long)(kb + k) * N3 + nbase + c];
        }
        __syncthreads();
#pragma unroll
        for (int k = 0; k < 16; k++) {
            float a[8];
#pragma unroll
            for (int i = 0; i < 8; i++) a[i] = As[ty * 8 + i][k];
            float4 bv = *(float4*)&Bs[k][tx * 4];
#pragma unroll
            for (int i = 0; i < 8; i++) {
                acc[i][0] += a[i] * bv.x;
                acc[i][1] += a[i] * bv.y;
                acc[i][2] += a[i] * bv.z;
                acc[i][3] += a[i] * bv.w;
            }
        }
        __syncthreads();
    }

    // epilogue: bias + scatter
    float bj[4];
#pragma unroll
    for (int j = 0; j < 4; j++) bj[j] = bias[nbase + tx * 4 + j];

#pragma unroll
    for (int i = 0; i < 8; i++) {
        int row = rbase + ty * 8 + i;
        int b = row >> 11, s = row & 2047;
#pragma unroll
        for (int j = 0; j < 4; j++) {
            int col = nbase + tx * 4 + j;
            float v = acc[i][j] + bj[j];
            int which = col >> 10;
            int d = col & 1023;
            int h = d >> 6, e = d & 63;
            long long idx = (((long long)(b * HH + h)) * SS + s) * HD + e;
            if (which == 0)      g_q[idx] = v;
            else if (which == 1) out[P_OFF + idx] = v;            // present[0] = k
            else                 out[P_OFF + P_HALF + idx] = v;   // present[1] = v
        }
    }
}

// ---------------------------------------------------------------------------
// Kernel 2: causal attention for one (b, h, 64-query-row tile).
// Phase A: denominators (no max-shift needed: scores are O(1)).
// Phase B: recompute scores, write normalized attn, accumulate attn@V.
// ---------------------------------------------------------------------------
#define SMP 68
#define ATTN_SMEM (4 * 64 * SMP * 4 + 64 * 4)

__global__ __launch_bounds__(256) void attn_kernel(float* __restrict__ out) {
    extern __shared__ float sm[];
    float* sQ = sm;
    float* sK = sm + 64 * SMP;
    float* sV = sm + 2 * 64 * SMP;
    float* sS = sm + 3 * 64 * SMP;
    float* rs = sm + 4 * 64 * SMP;

    const int tid = threadIdx.x;
    const int tx = tid & 15, ty = tid >> 4;
    const int qt = blockIdx.x, h = blockIdx.y, b = blockIdx.z;
    const int qbase = qt * 64;
    const long long headoff = ((long long)(b * HH + h)) * SS * HD;

    const float* qptr = g_q + headoff + (long long)qbase * HD;
    const float* kptr = out + P_OFF + headoff;
    const float* vptr = out + P_OFF + P_HALF + headoff;
    float* attn_out = out + ATTN_OFF + ((long long)(b * HH + h)) * SS * SS;

    // load Q tile (64x64)
#pragma unroll
    for (int i = tid; i < 1024; i += 256) {
        int r = i >> 4, c = (i & 15) << 2;
        *(float4*)&sQ[r * SMP + c] = *(const float4*)&qptr[r * HD + c];
    }

    const int r0 = ty * 4;
    const int c0 = tx * 4;

    // ---------------- Phase A: row denominators ----------------
    float rpart[4] = {0.f, 0.f, 0.f, 0.f};
    for (int kt = 0; kt <= qt; kt++) {
        __syncthreads();
#pragma unroll
        for (int i = tid; i < 1024; i += 256) {
            int r = i >> 4, c = (i & 15) << 2;
            *(float4*)&sK[r * SMP + c] = *(const float4*)&kptr[(kt * 64 + r) * HD + c];
        }
        __syncthreads();

        float acc[4][4];
#pragma unroll
        for (int i = 0; i < 4; i++)
#pragma unroll
            for (int j = 0; j < 4; j++) acc[i][j] = 0.f;

#pragma unroll 4
        for (int d = 0; d < 64; d++) {
            float qf[4], kf[4];
#pragma unroll
            for (int i = 0; i < 4; i++) qf[i] = sQ[(r0 + i) * SMP + d];
#pragma unroll
            for (int j = 0; j < 4; j++) kf[j] = sK[(c0 + j) * SMP + d];
#pragma unroll
            for (int i = 0; i < 4; i++)
#pragma unroll
                for (int j = 0; j < 4; j++) acc[i][j] += qf[i] * kf[j];
        }
        const bool diag = (kt == qt);
#pragma unroll
        for (int i = 0; i < 4; i++)
#pragma unroll
            for (int j = 0; j < 4; j++) {
                float e = (diag && (c0 + j > r0 + i)) ? 0.f
                                                      : __expf(acc[i][j] * 0.125f);
                rpart[i] += e;
            }
    }
    // reduce across the 16 tx lanes (same ty stays within half-warp)
#pragma unroll
    for (int i = 0; i < 4; i++) {
        rpart[i] += __shfl_xor_sync(0xFFFFFFFFu, rpart[i], 1);
        rpart[i] += __shfl_xor_sync(0xFFFFFFFFu, rpart[i], 2);
        rpart[i] += __shfl_xor_sync(0xFFFFFFFFu, rpart[i], 4);
        rpart[i] += __shfl_xor_sync(0xFFFFFFFFu, rpart[i], 8);
    }
    if (tx == 0) {
#pragma unroll
        for (int i = 0; i < 4; i++) rs[r0 + i] = rpart[i];
    }
    __syncthreads();
    float rinv[4];
#pragma unroll
    for (int i = 0; i < 4; i++) rinv[i] = 1.0f / rs[r0 + i];

    // ---------------- Phase B: write attn + attn@V ----------------
    float ao[4][4];
#pragma unroll
    for (int i = 0; i < 4; i++)
#pragma unroll
        for (int j = 0; j < 4; j++) ao[i][j] = 0.f;

    for (int kt = 0; kt <= qt; kt++) {
        __syncthreads();
#pragma unroll
        for (int i = tid; i < 2048; i += 256) {
            int r = (i >> 4) & 63, c = (i & 15) << 2;
            if (i < 1024)
                *(float4*)&sK[r * SMP + c] = *(const float4*)&kptr[(kt * 64 + r) * HD + c];
            else
                *(float4*)&sV[r * SMP + c] = *(const float4*)&vptr[(kt * 64 + r) * HD + c];
        }
        __syncthreads();

        float acc[4][4];
#pragma unroll
        for (int i = 0; i < 4; i++)
#pragma unroll
            for (int j = 0; j < 4; j++) acc[i][j] = 0.f;

#pragma unroll 4
        for (int d = 0; d < 64; d++) {
            float qf[4], kf[4];
#pragma unroll
            for (int i = 0; i < 4; i++) qf[i] = sQ[(r0 + i) * SMP + d];
#pragma unroll
            for (int j = 0; j < 4; j++) kf[j] = sK[(c0 + j) * SMP + d];
#pragma unroll
            for (int i = 0; i < 4; i++)
#pragma unroll
                for (int j = 0; j < 4; j++) acc[i][j] += qf[i] * kf[j];
        }
        const bool diag = (kt == qt);
#pragma unroll
        for (int i = 0; i < 4; i++) {
#pragma unroll
            for (int j = 0; j < 4; j++) {
                float e = (diag && (c0 + j > r0 + i)) ? 0.f
                                                      : __expf(acc[i][j] * 0.125f);
                acc[i][j] = e * rinv[i];
            }
            float4 av = make_float4(acc[i][0], acc[i][1], acc[i][2], acc[i][3]);
            *(float4*)&sS[(r0 + i) * SMP + c0] = av;
            *(float4*)&attn_out[(long long)(qbase + r0 + i) * SS + kt * 64 + c0] = av;
        }
        __syncthreads();

        // AV: ao[r][e] += sS[r][j] * sV[j][e]
#pragma unroll 2
        for (int j = 0; j < 64; j++) {
            float sv[4];
#pragma unroll
            for (int i = 0; i < 4; i++) sv[i] = sS[(r0 + i) * SMP + j];
            float4 vv = *(float4*)&sV[j * SMP + c0];
#pragma unroll
            for (int i = 0; i < 4; i++) {
                ao[i][0] += sv[i] * vv.x;
                ao[i][1] += sv[i] * vv.y;
                ao[i][2] += sv[i] * vv.z;
                ao[i][3] += sv[i] * vv.w;
            }
        }
    }

    // zero-fill strictly-upper attn tiles
    float4 z = make_float4(0.f, 0.f, 0.f, 0.f);
    for (int col = (qt + 1) * 64 + c0; col < SS; col += 64) {
#pragma unroll
        for (int i = 0; i < 4; i++)
            *(float4*)&attn_out[(long long)(qbase + r0 + i) * SS + col] = z;
    }

    // write merged-head output to scratch
#pragma unroll
    for (int i = 0; i < 4; i++) {
        float4 av = make_float4(ao[i][0], ao[i][1], ao[i][2], ao[i][3]);
        *(float4*)&g_ah[((long long)(b * SS + qbase + r0 + i)) * DD + h * HD + c0] = av;
    }
}

// ---------------------------------------------------------------------------
// Kernel 3: output projection. g_ah[4096,1024] @ w_proj[1024,1024] + b_proj.
// ---------------------------------------------------------------------------
__global__ __launch_bounds__(256) void proj_gemm(const float* __restrict__ w,
                                                 const float* __restrict__ bias,
                                                 float* __restrict__ out) {
    __shared__ float As[128][17];
    __shared__ float Bs[16][68];
    const int tid = threadIdx.x;
    const int tx = tid & 15, ty = tid >> 4;
    const int rbase = blockIdx.y * 128;
    const int nbase = blockIdx.x * 64;

    float acc[8][4];
#pragma unroll
    for (int i = 0; i < 8; i++)
#pragma unroll
        for (int j = 0; j < 4; j++) acc[i][j] = 0.f;

    for (int kb = 0; kb < DD; kb += 16) {
#pragma unroll
        for (int i = tid; i < 512; i += 256) {
            int r = i >> 2, c = (i & 3) << 2;
            float4 v = *(const float4*)&g_ah[(long long)(rbase + r) * DD + kb + c];
            As[r][c + 0] = v.x; As[r][c + 1] = v.y;
            As[r][c + 2] = v.z; As[r][c + 3] = v.w;
        }
        {
            int k = tid >> 4, c = (tid & 15) << 2;
            *(float4*)&Bs[k][c] = *(const float4*)&w[(long long)(kb + k) * DD + nbase + c];
        }
        __syncthreads();
#pragma unroll
        for (int k = 0; k < 16; k++) {
            float a[8];
#pragma unroll
            for (int i = 0; i < 8; i++) a[i] = As[ty * 8 + i][k];
            float4 bv = *(float4*)&Bs[k][tx * 4];
#pragma unroll
            for (int i = 0; i < 8; i++) {
                acc[i][0] += a[i] * bv.x;
                acc[i][1] += a[i] * bv.y;
                acc[i][2] += a[i] * bv.z;
                acc[i][3] += a[i] * bv.w;
            }
        }
        __syncthreads();
    }

    float bj[4];
#pragma unroll
    for (int j = 0; j < 4; j++) bj[j] = bias[nbase + tx * 4 + j];
#pragma unroll
    for (int i = 0; i < 8; i++) {
        int row = rbase + ty * 8 + i;
        float4 v = make_float4(acc[i][0] + bj[0], acc[i][1] + bj[1],
                               acc[i][2] + bj[2], acc[i][3] + bj[3]);
        *(float4*)&out[(long long)row * DD + nbase + tx * 4] = v;
    }
}

// ---------------------------------------------------------------------------
extern "C" void kernel_launch(void* const* d_in, const int* in_sizes, int n_in,
                              void* d_out, int out_size) {
    const float* x      = (const float*)d_in[0];
    const float* w_attn = (const float*)d_in[1];
    const float* b_attn = (const float*)d_in[2];
    const float* w_proj = (const float*)d_in[3];
    const float* b_proj = (const float*)d_in[4];
    float* out = (float*)d_out;

    cudaFuncSetAttribute(attn_kernel, cudaFuncAttributeMaxDynamicSharedMemorySize,
                         ATTN_SMEM);

    // 1) QKV projection: writes g_q and present(k,v) in d_out
    qkv_gemm<<<dim3(N3 / 64, MROWS / 128), 256>>>(x, w_attn, b_attn, out);

    // 2) attention: writes attn region of d_out and g_ah
    attn_kernel<<<dim3(SS / 64, HH, BB), 256, ATTN_SMEM>>>(out);

    // 3) output projection: writes a region of d_out
    proj_gemm<<<dim3(DD / 64, MROWS / 128), 256>>>(w_proj, b_proj, out);
}

// round 4
// speedup vs baseline: 1.6283x; 1.5332x over previous
#include <cuda_runtime.h>

// Problem constants
#define BB 2
#define SS 2048
#define DD 1024
#define HH 16
#define HD 64
#define N3 (3 * DD)     // 3072
#define MROWS (BB * SS) // 4096

// d_out layout (concatenated flattened outputs, in reference return order)
#define A_SZ   ((long long)BB * SS * DD)           // 4,194,304
#define P_HALF ((long long)BB * HH * SS * HD)      // 4,194,304
#define P_OFF  (A_SZ)
#define ATTN_OFF (A_SZ + 2 * P_HALF)               // 12,582,912

// Scratch (device globals — no allocations allowed)
__device__ float g_q[BB * HH * SS * HD];   // q in [B,H,S,hd]
__device__ float g_ah[MROWS * DD];         // merged-head attention output [B*S, D]
__device__ float g_rinv[BB * HH * SS];     // per-row 1/sum(exp)

// ---------------------------------------------------------------------------
// Kernel 1: QKV projection. x[4096,1024] @ w_attn[1024,3072] + b_attn.
// 128x128 tile per block, 256 threads, 8x8 per thread, K-tile 16.
// A stored k-major (transposed) in smem so both operands use LDS.128.
// Epilogue scatters q -> g_q, k/v -> present region of d_out ([B,H,S,hd]).
// ---------------------------------------------------------------------------
__global__ __launch_bounds__(256) void qkv_gemm(const float* __restrict__ x,
                                                const float* __restrict__ w,
                                                const float* __restrict__ bias,
                                                float* __restrict__ out) {
    __shared__ float As[16][132];   // As[k][r]
    __shared__ float Bs[16][132];   // Bs[k][c]
    const int tid = threadIdx.x;
    const int tx = tid & 15, ty = tid >> 4;
    const int rbase = blockIdx.y * 128;
    const int nbase = blockIdx.x * 128;

    float acc[8][8];
#pragma unroll
    for (int i = 0; i < 8; i++)
#pragma unroll
        for (int j = 0; j < 8; j++) acc[i][j] = 0.f;

    for (int kb = 0; kb < DD; kb += 16) {
        // A tile: 128 rows x 16 k -> transposed into As[k][r]
#pragma unroll
        for (int it = 0; it < 2; it++) {
            int i = tid + it * 256;
            int r = i >> 2, cq = (i & 3) << 2;
            float4 v = *(const float4*)&x[(long long)(rbase + r) * DD + kb + cq];
            As[cq + 0][r] = v.x; As[cq + 1][r] = v.y;
            As[cq + 2][r] = v.z; As[cq + 3][r] = v.w;
        }
        // B tile: 16 k x 128 cols, natural
#pragma unroll
        for (int it = 0; it < 2; it++) {
            int i = tid + it * 256;
            int k = i >> 5, cq = (i & 31) << 2;
            *(float4*)&Bs[k][cq] = *(const float4*)&w[(long long)(kb + k) * N3 + nbase + cq];
        }
        __syncthreads();
#pragma unroll
        for (int k = 0; k < 16; k++) {
            float4 a0 = *(float4*)&As[k][ty * 8];
            float4 a1 = *(float4*)&As[k][ty * 8 + 4];
            float4 b0 = *(float4*)&Bs[k][tx * 8];
            float4 b1 = *(float4*)&Bs[k][tx * 8 + 4];
            float af[8] = {a0.x, a0.y, a0.z, a0.w, a1.x, a1.y, a1.z, a1.w};
            float bf[8] = {b0.x, b0.y, b0.z, b0.w, b1.x, b1.y, b1.z, b1.w};
#pragma unroll
            for (int i = 0; i < 8; i++)
#pragma unroll
                for (int j = 0; j < 8; j++) acc[i][j] += af[i] * bf[j];
        }
        __syncthreads();
    }

    // epilogue: bias + scatter. Whole 128-col tile lies in one of q/k/v
    // (128 | 1024), each thread's 8 cols lie in one head (8 | 64).
    const int col0 = nbase + tx * 8;
    const int which = col0 >> 10;
    const int d0 = col0 & 1023;
    const int h = d0 >> 6, e0 = d0 & 63;
    float* dst = (which == 0) ? g_q : (which == 1) ? (out + P_OFF)
                                                   : (out + P_OFF + P_HALF);
    float bj[8];
#pragma unroll
    for (int j = 0; j < 8; j++) bj[j] = bias[col0 + j];

#pragma unroll
    for (int i = 0; i < 8; i++) {
        int row = rbase + ty * 8 + i;
        int b = row >> 11, s = row & 2047;
        long long idx = (((long long)(b * HH + h)) * SS + s) * HD + e0;
        float4 v0 = make_float4(acc[i][0] + bj[0], acc[i][1] + bj[1],
                                acc[i][2] + bj[2], acc[i][3] + bj[3]);
        float4 v1 = make_float4(acc[i][4] + bj[4], acc[i][5] + bj[5],
                                acc[i][6] + bj[6], acc[i][7] + bj[7]);
        *(float4*)&dst[idx] = v0;
        *(float4*)&dst[idx + 4] = v1;
    }
}

// ---------------------------------------------------------------------------
// Kernel 2: single-pass causal attention for one (b, h, 64-query-row tile).
// Computes scores ONCE: exp -> unnormalized write to attn region + rowsum
// accumulate + unnormalized A@V accumulate. Final scale of A@V by 1/rowsum.
// Normalization of the attn region happens in attn_rescale.
// ---------------------------------------------------------------------------
#define SMP 68
#define ATTN_SMEM ((4 * 64 * SMP + 64) * 4)

__global__ __launch_bounds__(256) void attn_fused(float* __restrict__ out) {
    extern __shared__ float sm[];
    float* sQT = sm;                   // [d][r]  64 x SMP
    float* sKT = sm + 64 * SMP;        // [d][c]
    float* sV  = sm + 2 * 64 * SMP;    // [j][e]  natural
    float* sST = sm + 3 * 64 * SMP;    // [j][r]  transposed exp scores
    float* rs  = sm + 4 * 64 * SMP;    // [64] rowsums

    const int tid = threadIdx.x;
    const int tx = tid & 15, ty = tid >> 4;
    const int qt = blockIdx.x, h = blockIdx.y, b = blockIdx.z;
    const int qbase = qt * 64;
    const int bh = b * HH + h;
    const long long headoff = (long long)bh * SS * HD;

    const float* qptr = g_q + headoff + (long long)qbase * HD;
    const float* kptr = out + P_OFF + headoff;
    const float* vptr = out + P_OFF + P_HALF + headoff;
    float* attn_out = out + ATTN_OFF + (long long)bh * SS * SS;

    // load Q tile transposed: sQT[d][r]
#pragma unroll
    for (int it = 0; it < 4; it++) {
        int i = tid + it * 256;
        int r = i >> 4, cq = (i & 15) << 2;
        float4 v = *(const float4*)&qptr[r * HD + cq];
        sQT[(cq + 0) * SMP + r] = v.x; sQT[(cq + 1) * SMP + r] = v.y;
        sQT[(cq + 2) * SMP + r] = v.z; sQT[(cq + 3) * SMP + r] = v.w;
    }

    const int r0 = ty * 4;
    const int c0 = tx * 4;

    float rpart[4] = {0.f, 0.f, 0.f, 0.f};
    float ao[4][4];
#pragma unroll
    for (int i = 0; i < 4; i++)
#pragma unroll
        for (int j = 0; j < 4; j++) ao[i][j] = 0.f;

    for (int kt = 0; kt <= qt; kt++) {
        __syncthreads();   // protect K/V/S tiles from previous iteration's readers
        // K transposed, V natural
#pragma unroll
        for (int it = 0; it < 4; it++) {
            int i = tid + it * 256;
            int r = i >> 4, cq = (i & 15) << 2;
            float4 kv = *(const float4*)&kptr[(kt * 64 + r) * HD + cq];
            sKT[(cq + 0) * SMP + r] = kv.x; sKT[(cq + 1) * SMP + r] = kv.y;
            sKT[(cq + 2) * SMP + r] = kv.z; sKT[(cq + 3) * SMP + r] = kv.w;
            *(float4*)&sV[r * SMP + cq] = *(const float4*)&vptr[(kt * 64 + r) * HD + cq];
        }
        __syncthreads();

        float acc[4][4];
#pragma unroll
        for (int i = 0; i < 4; i++)
#pragma unroll
            for (int j = 0; j < 4; j++) acc[i][j] = 0.f;

#pragma unroll 8
        for (int d = 0; d < 64; d++) {
            float4 qf = *(float4*)&sQT[d * SMP + r0];
            float4 kf = *(float4*)&sKT[d * SMP + c0];
            float qa[4] = {qf.x, qf.y, qf.z, qf.w};
            float ka[4] = {kf.x, kf.y, kf.z, kf.w};
#pragma unroll
            for (int i = 0; i < 4; i++)
#pragma unroll
                for (int j = 0; j < 4; j++) acc[i][j] += qa[i] * ka[j];
        }

        const bool diag = (kt == qt);
#pragma unroll
        for (int i = 0; i < 4; i++) {
#pragma unroll
            for (int j = 0; j < 4; j++) {
                float e = (diag && (c0 + j > r0 + i)) ? 0.f
                                                      : __expf(acc[i][j] * 0.125f);
                acc[i][j] = e;
                rpart[i] += e;
            }
            // unnormalized exp -> gmem (rescaled later)
            *(float4*)&attn_out[(long long)(qbase + r0 + i) * SS + kt * 64 + c0] =
                make_float4(acc[i][0], acc[i][1], acc[i][2], acc[i][3]);
        }
        // store S transposed: sST[c][r]
#pragma unroll
        for (int j = 0; j < 4; j++)
            *(float4*)&sST[(c0 + j) * SMP + r0] =
                make_float4(acc[0][j], acc[1][j], acc[2][j], acc[3][j]);
        __syncthreads();

        // unnormalized A@V: ao[i][e] += S[r0+i][j] * V[j][e]
#pragma unroll 4
        for (int j = 0; j < 64; j++) {
            float4 sv = *(float4*)&sST[j * SMP + r0];
            float4 vv = *(float4*)&sV[j * SMP + c0];
            float sa[4] = {sv.x, sv.y, sv.z, sv.w};
            ao[0][0] += sa[0] * vv.x; ao[0][1] += sa[0] * vv.y;
            ao[0][2] += sa[0] * vv.z; ao[0][3] += sa[0] * vv.w;
            ao[1][0] += sa[1] * vv.x; ao[1][1] += sa[1] * vv.y;
            ao[1][2] += sa[1] * vv.z; ao[1][3] += sa[1] * vv.w;
            ao[2][0] += sa[2] * vv.x; ao[2][1] += sa[2] * vv.y;
            ao[2][2] += sa[2] * vv.z; ao[2][3] += sa[2] * vv.w;
            ao[3][0] += sa[3] * vv.x; ao[3][1] += sa[3] * vv.y;
            ao[3][2] += sa[3] * vv.z; ao[3][3] += sa[3] * vv.w;
        }
    }

    // rowsum reduce across the 16 tx lanes (same ty stays within half-warp)
#pragma unroll
    for (int i = 0; i < 4; i++) {
        rpart[i] += __shfl_xor_sync(0xFFFFFFFFu, rpart[i], 1);
        rpart[i] += __shfl_xor_sync(0xFFFFFFFFu, rpart[i], 2);
        rpart[i] += __shfl_xor_sync(0xFFFFFFFFu, rpart[i], 4);
        rpart[i] += __shfl_xor_sync(0xFFFFFFFFu, rpart[i], 8);
    }
    if (tx == 0) {
#pragma unroll
        for (int i = 0; i < 4; i++) rs[r0 + i] = rpart[i];
    }
    __syncthreads();

    if (tid < 64) g_rinv[bh * SS + qbase + tid] = 1.0f / rs[tid];

    float rinv[4];
#pragma unroll
    for (int i = 0; i < 4; i++) rinv[i] = 1.0f / rs[r0 + i];

    // merged-head output (normalized)
#pragma unroll
    for (int i = 0; i < 4; i++) {
        float4 av = make_float4(ao[i][0] * rinv[i], ao[i][1] * rinv[i],
                                ao[i][2] * rinv[i], ao[i][3] * rinv[i]);
        *(float4*)&g_ah[((long long)(b * SS + qbase + r0 + i)) * DD + h * HD + c0] = av;
    }
}

// ---------------------------------------------------------------------------
// Kernel 3: normalize attn rows (multiply by 1/rowsum) and zero-fill the
// strictly-upper tile region. Pure streaming.
// Block = (qt, bh): 64 rows x 2048 cols.
// ---------------------------------------------------------------------------
__global__ __launch_bounds__(256) void attn_rescale(float* __restrict__ out) {
    __shared__ float srinv[64];
    const int tid = threadIdx.x;
    const int qt = blockIdx.x, bh = blockIdx.y;
    float* base = out + ATTN_OFF + (long long)bh * SS * SS + (long long)qt * 64 * SS;
    if (tid < 64) srinv[tid] = g_rinv[bh * SS + qt * 64 + tid];
    __syncthreads();

    const int Lc = (qt + 1) * 64;   // cols < Lc: scale; cols >= Lc: zero
    const float4 z = make_float4(0.f, 0.f, 0.f, 0.f);
    // 64 rows x 512 float4 per row = 32768 float4, 256 threads -> 128 iters
    for (int i = tid; i < 64 * 512; i += 256) {
        int r = i >> 9;
        int c4 = (i & 511) << 2;
        float4* p = (float4*)&base[(long long)r * SS + c4];
        if (c4 < Lc) {
            float rv = srinv[r];
            float4 v = *p;
            v.x *= rv; v.y *= rv; v.z *= rv; v.w *= rv;
            *p = v;
        } else {
            *p = z;
        }
    }
}

// ---------------------------------------------------------------------------
// Kernel 4: output projection. g_ah[4096,1024] @ w_proj[1024,1024] + b_proj.
// Same 128x128 scheme as qkv_gemm.
// ---------------------------------------------------------------------------
__global__ __launch_bounds__(256) void proj_gemm(const float* __restrict__ w,
                                                 const float* __restrict__ bias,
                                                 float* __restrict__ out) {
    __shared__ float As[16][132];
    __shared__ float Bs[16][132];
    const int tid = threadIdx.x;
    const int tx = tid & 15, ty = tid >> 4;
    const int rbase = blockIdx.y * 128;
    const int nbase = blockIdx.x * 128;

    float acc[8][8];
#pragma unroll
    for (int i = 0; i < 8; i++)
#pragma unroll
        for (int j = 0; j < 8; j++) acc[i][j] = 0.f;

    for (int kb = 0; kb < DD; kb += 16) {
#pragma unroll
        for (int it = 0; it < 2; it++) {
            int i = tid + it * 256;
            int r = i >> 2, cq = (i & 3) << 2;
            float4 v = *(const float4*)&g_ah[(long long)(rbase + r) * DD + kb + cq];
            As[cq + 0][r] = v.x; As[cq + 1][r] = v.y;
            As[cq + 2][r] = v.z; As[cq + 3][r] = v.w;
        }
#pragma unroll
        for (int it = 0; it < 2; it++) {
            int i = tid + it * 256;
            int k = i >> 5, cq = (i & 31) << 2;
            *(float4*)&Bs[k][cq] = *(const float4*)&w[(long long)(kb + k) * DD + nbase + cq];
        }
        __syncthreads();
#pragma unroll
        for (int k = 0; k < 16; k++) {
            float4 a0 = *(float4*)&As[k][ty * 8];
            float4 a1 = *(float4*)&As[k][ty * 8 + 4];
            float4 b0 = *(float4*)&Bs[k][tx * 8];
            float4 b1 = *(float4*)&Bs[k][tx * 8 + 4];
            float af[8] = {a0.x, a0.y, a0.z, a0.w, a1.x, a1.y, a1.z, a1.w};
            float bf[8] = {b0.x, b0.y, b0.z, b0.w, b1.x, b1.y, b1.z, b1.w};
#pragma unroll
            for (int i = 0; i < 8; i++)
#pragma unroll
                for (int j = 0; j < 8; j++) acc[i][j] += af[i] * bf[j];
        }
        __syncthreads();
    }

    float bj[8];
#pragma unroll
    for (int j = 0; j < 8; j++) bj[j] = bias[nbase + tx * 8 + j];
#pragma unroll
    for (int i = 0; i < 8; i++) {
        int row = rbase + ty * 8 + i;
        float4 v0 = make_float4(acc[i][0] + bj[0], acc[i][1] + bj[1],
                                acc[i][2] + bj[2], acc[i][3] + bj[3]);
        float4 v1 = make_float4(acc[i][4] + bj[4], acc[i][5] + bj[5],
                                acc[i][6] + bj[6], acc[i][7] + bj[7]);
        *(float4*)&out[(long long)row * DD + nbase + tx * 8] = v0;
        *(float4*)&out[(long long)row * DD + nbase + tx * 8 + 4] = v1;
    }
}

// ---------------------------------------------------------------------------
extern "C" void kernel_launch(void* const* d_in, const int* in_sizes, int n_in,
                              void* d_out, int out_size) {
    const float* x      = (const float*)d_in[0];
    const float* w_attn = (const float*)d_in[1];
    const float* b_attn = (const float*)d_in[2];
    const float* w_proj = (const float*)d_in[3];
    const float* b_proj = (const float*)d_in[4];
    float* out = (float*)d_out;

    cudaFuncSetAttribute(attn_fused, cudaFuncAttributeMaxDynamicSharedMemorySize,
                         ATTN_SMEM);

    // 1) QKV projection: writes g_q and present(k,v) in d_out
    qkv_gemm<<<dim3(N3 / 128, MROWS / 128), 256>>>(x, w_attn, b_attn, out);

    // 2) attention: writes unnormalized attn region + g_ah + g_rinv
    attn_fused<<<dim3(SS / 64, HH, BB), 256, ATTN_SMEM>>>(out);

    // 3) normalize attn + zero-fill upper triangle
    attn_rescale<<<dim3(SS / 64, BB * HH), 256>>>(out);

    // 4) output projection: writes a region of d_out
    proj_gemm<<<dim3(DD / 128, MROWS / 128), 256>>>(w_proj, b_proj, out);
}

// round 6
// speedup vs baseline: 2.5914x; 1.5915x over previous
#include <cuda_runtime.h>
#include <cuda_bf16.h>
#include <cstdint>

// Problem constants
#define BB 2
#define SS 2048
#define DD 1024
#define HH 16
#define HD 64
#define N3 3072
#define MROWS 4096

// d_out layout
#define A_SZ   ((long long)BB * SS * DD)
#define P_HALF ((long long)BB * HH * SS * HD)
#define P_OFF  (A_SZ)
#define ATTN_OFF (A_SZ + 2 * P_HALF)

// Scratch (device globals)
__device__ float g_q[BB * HH * SS * HD];
__device__ float g_ah[MROWS * DD];
__device__ __nv_bfloat16 g_xhi[MROWS * DD], g_xlo[MROWS * DD];
__device__ __nv_bfloat16 g_wahi[N3 * DD],  g_walo[N3 * DD];    // w_attn^T [3072,1024]
__device__ __nv_bfloat16 g_wphi[DD * DD],  g_wplo[DD * DD];    // w_proj^T [1024,1024]
__device__ __nv_bfloat16 g_ahhi[MROWS * DD], g_ahlo[MROWS * DD];

// ====================== base-PTX helpers ====================================
__device__ __forceinline__ uint32_t smem_u32(const void* p) {
    uint32_t a;
    asm("{ .reg .u64 t; cvta.to.shared.u64 t, %1; cvt.u32.u64 %0, t; }"
        : "=r"(a) : "l"(p));
    return a;
}
__device__ __forceinline__ void ldsm4(uint32_t* r, uint32_t a) {
    asm volatile("ldmatrix.sync.aligned.m8n8.x4.shared.b16 {%0,%1,%2,%3}, [%4];"
                 : "=r"(r[0]), "=r"(r[1]), "=r"(r[2]), "=r"(r[3]) : "r"(a));
}
__device__ __forceinline__ void ldsm2(uint32_t* r, uint32_t a) {
    asm volatile("ldmatrix.sync.aligned.m8n8.x2.shared.b16 {%0,%1}, [%2];"
                 : "=r"(r[0]), "=r"(r[1]) : "r"(a));
}
__device__ __forceinline__ void ldsm2t(uint32_t* r, uint32_t a) {
    asm volatile("ldmatrix.sync.aligned.m8n8.x2.trans.shared.b16 {%0,%1}, [%2];"
                 : "=r"(r[0]), "=r"(r[1]) : "r"(a));
}
__device__ __forceinline__ void mma_bf16(float* d, const uint32_t* a, const uint32_t* b) {
    asm volatile("mma.sync.aligned.m16n8k16.row.col.f32.bf16.bf16.f32 "
                 "{%0,%1,%2,%3}, {%4,%5,%6,%7}, {%8,%9}, {%0,%1,%2,%3};"
                 : "+f"(d[0]), "+f"(d[1]), "+f"(d[2]), "+f"(d[3])
                 : "r"(a[0]), "r"(a[1]), "r"(a[2]), "r"(a[3]), "r"(b[0]), "r"(b[1]));
}
__device__ __forceinline__ void sp(float x, uint16_t& h, uint16_t& l) {
    __nv_bfloat16 bh = __float2bfloat16_rn(x);
    h = __bfloat16_as_ushort(bh);
    l = __bfloat16_as_ushort(__float2bfloat16_rn(x - __bfloat162float(bh)));
}
__device__ __forceinline__ uint32_t pk(uint16_t a, uint16_t b) {
    return (uint32_t)a | ((uint32_t)b << 16);
}

// ====================== bf16 split kernels ==================================
__global__ __launch_bounds__(256) void split_plain(const float* __restrict__ in,
                                                   __nv_bfloat16* __restrict__ hi,
                                                   __nv_bfloat16* __restrict__ lo, int n4) {
    int i = blockIdx.x * 256 + threadIdx.x;
    if (i >= n4) return;
    float4 v = ((const float4*)in)[i];
    uint16_t h0, h1, h2, h3, l0, l1, l2, l3;
    sp(v.x, h0, l0); sp(v.y, h1, l1); sp(v.z, h2, l2); sp(v.w, h3, l3);
    ((uint2*)hi)[i] = make_uint2(pk(h0, h1), pk(h2, h3));
    ((uint2*)lo)[i] = make_uint2(pk(l0, l1), pk(l2, l3));
}

// transpose split: in fp32 [1024 x N] row-major -> out bf16 [N x 1024]
__global__ __launch_bounds__(256) void split_T(const float* __restrict__ in,
                                               __nv_bfloat16* __restrict__ hi,
                                               __nv_bfloat16* __restrict__ lo, int N) {
    __shared__ float t[32][33];
    int nb = blockIdx.x * 32, kb = blockIdx.y * 32;
#pragma unroll
    for (int r = 0; r < 4; r++)
        t[threadIdx.y + r * 8][threadIdx.x] =
            in[(long long)(kb + threadIdx.y + r * 8) * N + nb + threadIdx.x];
    __syncthreads();
#pragma unroll
    for (int r = 0; r < 4; r++) {
        int n = nb + threadIdx.y + r * 8;
        float v = t[threadIdx.x][threadIdx.y + r * 8];
        uint16_t h, l;
        sp(v, h, l);
        long long o = (long long)n * 1024 + kb + threadIdx.x;
        hi[o] = __ushort_as_bfloat16(h);
        lo[o] = __ushort_as_bfloat16(l);
    }
}

// ====================== mma.sync GEMM (bf16x3) ==============================
// D[128,128] = A[128,1024] @ B[N,K]^T, A/B pre-split bf16 hi/lo, K-major.
#define GPB 144                      // padded row bytes (72 bf16)
#define GT_TILEB (128 * GPB)         // 18432
#define GEMM_SMEM (4 * GT_TILEB)     // 73728

template <int MODE>
__global__ __launch_bounds__(256) void gemm_mma(
    const __nv_bfloat16* __restrict__ Ahi, const __nv_bfloat16* __restrict__ Alo,
    const __nv_bfloat16* __restrict__ Bhi, const __nv_bfloat16* __restrict__ Blo,
    const float* __restrict__ bias, float* __restrict__ out) {
    extern __shared__ char sm[];
    const uint32_t sb = smem_u32(sm);
    const int tid = threadIdx.x;
    const int lane = tid & 31, warp = tid >> 5;
    const int wm = warp >> 1, wn = warp & 1;          // 4 x 2 warps
    const int qr = lane >> 2, qc2 = (lane & 3) * 2;
    const int nbase = blockIdx.x * 128, rbase = blockIdx.y * 128;

    float o[2][8][4];
#pragma unroll
    for (int a = 0; a < 2; a++)
#pragma unroll
        for (int b = 0; b < 8; b++)
#pragma unroll
            for (int c = 0; c < 4; c++) o[a][b][c] = 0.f;

    const int lr = tid >> 1, lc = (tid & 1) * 32;
    const long long aoff = (long long)(rbase + lr) * 1024 + lc;
    const long long boff = (long long)(nbase + lr) * 1024 + lc;
    uint4* dA0 = (uint4*)(sm + lr * GPB + lc * 2);
    uint4* dA1 = (uint4*)(sm + GT_TILEB + lr * GPB + lc * 2);
    uint4* dB0 = (uint4*)(sm + 2 * GT_TILEB + lr * GPB + lc * 2);
    uint4* dB1 = (uint4*)(sm + 3 * GT_TILEB + lr * GPB + lc * 2);

    for (int ks = 0; ks < 16; ks++) {
        __syncthreads();
        const int kb = ks * 64;
        const uint4* pAh = (const uint4*)(Ahi + aoff + kb);
        const uint4* pAl = (const uint4*)(Alo + aoff + kb);
        const uint4* pBh = (const uint4*)(Bhi + boff + kb);
        const uint4* pBl = (const uint4*)(Blo + boff + kb);
#pragma unroll
        for (int c = 0; c < 4; c++) {
            dA0[c] = pAh[c]; dA1[c] = pAl[c];
            dB0[c] = pBh[c]; dB1[c] = pBl[c];
        }
        __syncthreads();

#pragma unroll
        for (int k16 = 0; k16 < 4; k16++) {
            uint32_t ah[2][4], al[2][4];
#pragma unroll
            for (int mt = 0; mt < 2; mt++) {
                uint32_t r = wm * 32 + mt * 16 + (lane & 7) + ((lane >> 3) & 1) * 8;
                uint32_t c = k16 * 16 + (lane >> 4) * 8;
                uint32_t off = r * GPB + c * 2;
                ldsm4(ah[mt], sb + off);
                ldsm4(al[mt], sb + GT_TILEB + off);
            }
#pragma unroll
            for (int nt = 0; nt < 8; nt++) {
                uint32_t bh[2], bl[2];
                uint32_t n = wn * 64 + nt * 8 + (lane & 7);
                uint32_t c = k16 * 16 + ((lane >> 3) & 1) * 8;
                uint32_t off = n * GPB + c * 2;
                ldsm2(bh, sb + 2 * GT_TILEB + off);
                ldsm2(bl, sb + 3 * GT_TILEB + off);
#pragma unroll
                for (int mt = 0; mt < 2; mt++) {
                    mma_bf16(o[mt][nt], ah[mt], bh);
                    mma_bf16(o[mt][nt], ah[mt], bl);
                    mma_bf16(o[mt][nt], al[mt], bh);
                }
            }
        }
    }

    // epilogue
#pragma unroll
    for (int nt = 0; nt < 8; nt++) {
        const int cg = nbase + wn * 64 + nt * 8 + qc2;
        const float b0 = bias[cg], b1 = bias[cg + 1];
#pragma unroll
        for (int mt = 0; mt < 2; mt++) {
            int r0 = rbase + wm * 32 + mt * 16 + qr;
            int r1 = r0 + 8;
            float2 v0 = make_float2(o[mt][nt][0] + b0, o[mt][nt][1] + b1);
            float2 v1 = make_float2(o[mt][nt][2] + b0, o[mt][nt][3] + b1);
            if (MODE == 0) {
                int which = cg >> 10, d0 = cg & 1023;
                int hh = d0 >> 6, e0 = d0 & 63;
                float* dst = (which == 0) ? g_q
                           : (which == 1) ? (out + P_OFF) : (out + P_OFF + P_HALF);
                int b_0 = r0 >> 11, s_0 = r0 & 2047;
                int b_1 = r1 >> 11, s_1 = r1 & 2047;
                *(float2*)&dst[(((long long)(b_0 * HH + hh)) * SS + s_0) * HD + e0] = v0;
                *(float2*)&dst[(((long long)(b_1 * HH + hh)) * SS + s_1) * HD + e0] = v1;
            } else {
                *(float2*)&out[(long long)r0 * DD + cg] = v0;
                *(float2*)&out[(long long)r1 * DD + cg] = v1;
            }
        }
    }
}

// ====================== attention (mma.sync, 2-pass recompute) ==============
#define APB 144
#define AT_TILEB (64 * APB)          // 9216
#define ATTN_SMEM (6 * AT_TILEB + 256)

// convert 64x64 fp32 tile (row stride HD) -> bf16 hi/lo smem tiles
__device__ __forceinline__ void cvt_tile(const float* __restrict__ g,
                                         char* hi, char* lo, int tid) {
    const int r = tid >> 1, c0 = (tid & 1) * 32;
    const float4* src = (const float4*)(g + r * HD + c0);
    uint32_t* dh = (uint32_t*)(hi + r * APB + c0 * 2);
    uint32_t* dl = (uint32_t*)(lo + r * APB + c0 * 2);
#pragma unroll
    for (int i = 0; i < 8; i++) {
        float4 v = src[i];
        uint16_t h0, h1, h2, h3, l0, l1, l2, l3;
        sp(v.x, h0, l0); sp(v.y, h1, l1); sp(v.z, h2, l2); sp(v.w, h3, l3);
        dh[i * 2] = pk(h0, h1); dh[i * 2 + 1] = pk(h2, h3);
        dl[i * 2] = pk(l0, l1); dl[i * 2 + 1] = pk(l2, l3);
    }
}

__global__ __launch_bounds__(128) void attn_mma(float* __restrict__ out) {
    extern __shared__ char sm[];
    const uint32_t sb = smem_u32(sm);
    char* sQh = sm;
    char* sQl = sm + AT_TILEB;
    char* sKh = sm + 2 * AT_TILEB;
    char* sKl = sm + 3 * AT_TILEB;
    char* sVh = sm + 4 * AT_TILEB;
    char* sVl = sm + 5 * AT_TILEB;
    float* srinv = (float*)(sm + 6 * AT_TILEB);

    const int tid = threadIdx.x;
    const int lane = tid & 31, wm = tid >> 5;      // 4 warps, m16 each
    const int qr = lane >> 2, qc2 = (lane & 3) * 2;
    const int qt = blockIdx.x, h = blockIdx.y, b = blockIdx.z;
    const int qbase = qt * 64, bh_ = b * HH + h;
    const long long headoff = (long long)bh_ * SS * HD;
    const float* qg = g_q + headoff + (long long)qbase * HD;
    const float* kg = out + P_OFF + headoff;
    const float* vg = out + P_OFF + P_HALF + headoff;
    float* attn_out = out + ATTN_OFF + (long long)bh_ * SS * SS;

    cvt_tile(qg, sQh, sQl, tid);
    __syncthreads();

    // preload Q fragments (row-major A frags, m16 x k16 x 4 chunks)
    uint32_t qh[4][4], ql[4][4];
#pragma unroll
    for (int j = 0; j < 4; j++) {
        uint32_t r = wm * 16 + (lane & 7) + ((lane >> 3) & 1) * 8;
        uint32_t c = j * 16 + (lane >> 4) * 8;
        uint32_t off = r * APB + c * 2;
        ldsm4(qh[j], sb + off);
        ldsm4(ql[j], sb + AT_TILEB + off);
    }

    const int r0g = qbase + wm * 16 + qr;
    const int r1g = r0g + 8;

    // ---------------- pass A: rowsums ----------------
    float rs0 = 0.f, rs1 = 0.f;
    for (int kt = 0; kt <= qt; kt++) {
        __syncthreads();
        cvt_tile(kg + (long long)kt * 64 * HD, sKh, sKl, tid);
        __syncthreads();
#pragma unroll
        for (int nt = 0; nt < 8; nt++) {
            float s[4] = {0.f, 0.f, 0.f, 0.f};
#pragma unroll
            for (int j = 0; j < 4; j++) {
                uint32_t bh2[2], bl2[2];
                uint32_t n = nt * 8 + (lane & 7);
                uint32_t c = j * 16 + ((lane >> 3) & 1) * 8;
                uint32_t off = n * APB + c * 2;
                ldsm2(bh2, sb + 2 * AT_TILEB + off);
                ldsm2(bl2, sb + 3 * AT_TILEB + off);
                mma_bf16(s, qh[j], bh2);
                mma_bf16(s, qh[j], bl2);
                mma_bf16(s, ql[j], bh2);
            }
            const int cg = kt * 64 + nt * 8 + qc2;
            if (cg <= r0g)     rs0 += __expf(s[0] * 0.125f);
            if (cg + 1 <= r0g) rs0 += __expf(s[1] * 0.125f);
            if (cg <= r1g)     rs1 += __expf(s[2] * 0.125f);
            if (cg + 1 <= r1g) rs1 += __expf(s[3] * 0.125f);
        }
    }
    rs0 += __shfl_xor_sync(0xFFFFFFFFu, rs0, 1);
    rs0 += __shfl_xor_sync(0xFFFFFFFFu, rs0, 2);
    rs1 += __shfl_xor_sync(0xFFFFFFFFu, rs1, 1);
    rs1 += __shfl_xor_sync(0xFFFFFFFFu, rs1, 2);
    if ((lane & 3) == 0) {
        srinv[wm * 16 + qr] = 1.0f / rs0;
        srinv[wm * 16 + qr + 8] = 1.0f / rs1;
    }
    __syncthreads();
    const float ri0 = srinv[wm * 16 + qr];
    const float ri1 = srinv[wm * 16 + qr + 8];

    // ---------------- pass B: write attn + A@V ----------------
    float o[8][4];
#pragma unroll
    for (int a = 0; a < 8; a++)
#pragma unroll
        for (int c = 0; c < 4; c++) o[a][c] = 0.f;

    for (int kt = 0; kt <= qt; kt++) {
        __syncthreads();
        cvt_tile(kg + (long long)kt * 64 * HD, sKh, sKl, tid);
        cvt_tile(vg + (long long)kt * 64 * HD, sVh, sVl, tid);
        __syncthreads();

        uint32_t sah[4][4], sal[4][4];
#pragma unroll
        for (int nt = 0; nt < 8; nt++) {
            float s[4] = {0.f, 0.f, 0.f, 0.f};
#pragma unroll
            for (int j = 0; j < 4; j++) {
                uint32_t bh2[2], bl2[2];
                uint32_t n = nt * 8 + (lane & 7);
                uint32_t c = j * 16 + ((lane >> 3) & 1) * 8;
                uint32_t off = n * APB + c * 2;
                ldsm2(bh2, sb + 2 * AT_TILEB + off);
                ldsm2(bl2, sb + 3 * AT_TILEB + off);
                mma_bf16(s, qh[j], bh2);
                mma_bf16(s, qh[j], bl2);
                mma_bf16(s, ql[j], bh2);
            }
            const int cg = kt * 64 + nt * 8 + qc2;
            float e0 = (cg > r0g)     ? 0.f : __expf(s[0] * 0.125f) * ri0;
            float e1 = (cg + 1 > r0g) ? 0.f : __expf(s[1] * 0.125f) * ri0;
            float e2 = (cg > r1g)     ? 0.f : __expf(s[2] * 0.125f) * ri1;
            float e3 = (cg + 1 > r1g) ? 0.f : __expf(s[3] * 0.125f) * ri1;
            *(float2*)&attn_out[(long long)r0g * SS + cg] = make_float2(e0, e1);
            *(float2*)&attn_out[(long long)r1g * SS + cg] = make_float2(e2, e3);
            // build S fragments for AV (A row-major m16 x k16; k = key idx)
            uint16_t h0, h1, h2, h3, l0, l1, l2, l3;
            sp(e0, h0, l0); sp(e1, h1, l1); sp(e2, h2, l2); sp(e3, h3, l3);
            const int j = nt >> 1, half = (nt & 1) * 2;
            sah[j][half]     = pk(h0, h1); sah[j][half + 1] = pk(h2, h3);
            sal[j][half]     = pk(l0, l1); sal[j][half + 1] = pk(l2, l3);
        }
#pragma unroll
        for (int j = 0; j < 4; j++) {
#pragma unroll
            for (int nt2 = 0; nt2 < 8; nt2++) {
                uint32_t vh2[2], vl2[2];
                uint32_t key = j * 16 + ((lane >> 3) & 1) * 8 + (lane & 7);
                uint32_t off = key * APB + nt2 * 16;   // nt2*8 bf16 = 16B
                ldsm2t(vh2, sb + 4 * AT_TILEB + off);
                ldsm2t(vl2, sb + 5 * AT_TILEB + off);
                mma_bf16(o[nt2], sah[j], vh2);
                mma_bf16(o[nt2], sah[j], vl2);
                mma_bf16(o[nt2], sal[j], vh2);
            }
        }
    }

    // write merged-head output
#pragma unroll
    for (int nt2 = 0; nt2 < 8; nt2++) {
        const int col = h * 64 + nt2 * 8 + qc2;
        const long long gr0 = (long long)(b * SS + qbase + wm * 16 + qr);
        *(float2*)&g_ah[gr0 * DD + col] = make_float2(o[nt2][0], o[nt2][1]);
        *(float2*)&g_ah[(gr0 + 8) * DD + col] = make_float2(o[nt2][2], o[nt2][3]);
    }
}

// ====================== upper-triangle zero fill ============================
__global__ __launch_bounds__(256) void attn_fill(float* __restrict__ out) {
    const int tid = threadIdx.x;
    const int qt = blockIdx.x, bh = blockIdx.y;
    const int Lc = (qt + 1) * 64;
    const int per4 = (SS - Lc) >> 2;
    if (per4 == 0) return;
    float* base = out + ATTN_OFF + (long long)bh * SS * SS + (long long)qt * 64 * SS;
    const float4 z = make_float4(0.f, 0.f, 0.f, 0.f);
    for (int i = tid; i < 64 * per4; i += 256) {
        int r = i / per4;
        int c = Lc + (i - r * per4) * 4;
        *(float4*)&base[(long long)r * SS + c] = z;
    }
}

// ====================== launch ==============================================
extern "C" void kernel_launch(void* const* d_in, const int* in_sizes, int n_in,
                              void* d_out, int out_size) {
    const float* x      = (const float*)d_in[0];
    const float* w_attn = (const float*)d_in[1];
    const float* b_attn = (const float*)d_in[2];
    const float* w_proj = (const float*)d_in[3];
    const float* b_proj = (const float*)d_in[4];
    float* out = (float*)d_out;

    __nv_bfloat16 *xhi, *xlo, *wahi, *walo, *wphi, *wplo, *ahhi, *ahlo;
    float* gah;
    cudaGetSymbolAddress((void**)&xhi,  g_xhi);
    cudaGetSymbolAddress((void**)&xlo,  g_xlo);
    cudaGetSymbolAddress((void**)&wahi, g_wahi);
    cudaGetSymbolAddress((void**)&walo, g_walo);
    cudaGetSymbolAddress((void**)&wphi, g_wphi);
    cudaGetSymbolAddress((void**)&wplo, g_wplo);
    cudaGetSymbolAddress((void**)&ahhi, g_ahhi);
    cudaGetSymbolAddress((void**)&ahlo, g_ahlo);
    cudaGetSymbolAddress((void**)&gah,  g_ah);

    cudaFuncSetAttribute(gemm_mma<0>, cudaFuncAttributeMaxDynamicSharedMemorySize, GEMM_SMEM);
    cudaFuncSetAttribute(gemm_mma<1>, cudaFuncAttributeMaxDynamicSharedMemorySize, GEMM_SMEM);
    cudaFuncSetAttribute(attn_mma, cudaFuncAttributeMaxDynamicSharedMemorySize, ATTN_SMEM);

    // 0) split inputs (weights transposed to [N,K])
    split_plain<<<(MROWS * DD / 4 + 255) / 256, 256>>>(x, xhi, xlo, MROWS * DD / 4);
    split_T<<<dim3(N3 / 32, DD / 32), dim3(32, 8)>>>(w_attn, wahi, walo, N3);
    split_T<<<dim3(DD / 32, DD / 32), dim3(32, 8)>>>(w_proj, wphi, wplo, DD);

    // 1) QKV projection -> g_q + present(k,v)
    gemm_mma<0><<<dim3(N3 / 128, MROWS / 128), 256, GEMM_SMEM>>>(xhi, xlo, wahi, walo, b_attn, out);

    // 2) attention -> normalized attn region + g_ah
    attn_mma<<<dim3(SS / 64, HH, BB), 128, ATTN_SMEM>>>(out);

    // 3) zero-fill strictly-upper attn region
    attn_fill<<<dim3(SS / 64, BB * HH), 256>>>(out);

    // 4) output projection
    split_plain<<<(MROWS * DD / 4 + 255) / 256, 256>>>(gah, ahhi, ahlo, MROWS * DD / 4);
    gemm_mma<1><<<dim3(DD / 128, MROWS / 128), 256, GEMM_SMEM>>>(ahhi, ahlo, wphi, wplo, b_proj, out);
}